// round 3
// baseline (speedup 1.0000x reference)
#include <cuda_runtime.h>
#include <stdint.h>

#define FULL 0xffffffffu

// Flag written by the detection kernel each launch: 1 if member_mask is stored
// as int32 per element, 0 if stored as 1 byte (numpy bool) per element.
__device__ int g_mask_is_i32;

__global__ void detect_mask_kernel(const int* __restrict__ mask_as_i32, int n_i32) {
    __shared__ int bad;
    if (threadIdx.x == 0) bad = 0;
    __syncthreads();
    int local = 0;
    for (int i = threadIdx.x; i < n_i32; i += blockDim.x) {
        int v = mask_as_i32[i];
        if (v != 0 && v != 1) local = 1;
    }
    if (local) atomicOr(&bad, 1);
    __syncthreads();
    if (threadIdx.x == 0) g_mask_is_i32 = bad ? 0 : 1;
}

// 4 pairs per warp: lanes [8p, 8p+7] handle pair p of the warp's 4.
// Each lane owns 4 embedding dims (float4). D = 32, M = 16 hardcoded.
__global__ __launch_bounds__(256)
void bilinear_kernel(const int* __restrict__ item_inputs,
                     const int* __restrict__ member_ids,
                     const void* __restrict__ member_mask,
                     const float* __restrict__ user_table,
                     const float* __restrict__ item_table,
                     const float* __restrict__ W_bil,
                     const float* __restrict__ b_bil,
                     const float* __restrict__ b1,
                     const float* __restrict__ W1,
                     const float* __restrict__ W2,
                     const float* __restrict__ b2,
                     float* __restrict__ out,
                     int B)
{
    __shared__ float Ws[32 * 32];   // Ws[e*32 + d] = W_bil[d][e]  (transposed)
    __shared__ float W1s[8 * 96];
    __shared__ float b1s[8], W2s[8];
    __shared__ float sc[2];          // {b_bil, b2}

    const int tid = threadIdx.x;
    for (int i = tid; i < 1024; i += 256)
        Ws[(i & 31) * 32 + (i >> 5)] = W_bil[i];
    for (int i = tid; i < 768; i += 256)
        W1s[i] = W1[i];
    if (tid < 8) { b1s[tid] = b1[tid]; W2s[tid] = W2[tid]; }
    if (tid == 0) { sc[0] = b_bil[0]; sc[1] = b2[0]; }
    __syncthreads();

    const int warp = tid >> 5;
    const int lane = tid & 31;
    const int sub  = lane >> 3;     // which pair within warp (0..3)
    const int sl   = lane & 7;      // lane within pair (0..7), dims sl*4..sl*4+3
    const int sbase = lane & 24;    // sub * 8

    const int gb = (blockIdx.x * 8 + warp) * 4;  // first pair handled by this warp
    if (gb >= B) return;
    const int b  = gb + sub;
    const int bc = min(b, B - 1);

    const float bbil = sc[0];
    const float bb2  = sc[1];
    const bool mask_i32 = (g_mask_is_i32 != 0);

    // ---- item embedding (8 lanes of a subgroup read the same row, 16B apart) ----
    const int it = __ldg(item_inputs + bc);
    const float4 ie = *reinterpret_cast<const float4*>(item_table + (size_t)it * 32 + sl * 4);

    // ---- member ids + mask: 64 consecutive (id, mask) for the warp's 4 pairs ----
    // Each lane holds 2 members; mask packed into the id sign bit.
    int pk0, pk1;
    {
        long off = (long)gb * 16 + lane * 2;
        long maxoff = (long)B * 16 - 2;
        if (off > maxoff) off = maxoff;   // defensive clamp (B is a multiple of 4 anyway)
        int2 mi = *reinterpret_cast<const int2*>(member_ids + off);
        int m0, m1;
        if (mask_i32) {
            int2 mm = *reinterpret_cast<const int2*>((const int*)member_mask + off);
            m0 = mm.x; m1 = mm.y;
        } else {
            unsigned short s = *reinterpret_cast<const unsigned short*>(
                (const unsigned char*)member_mask + off);
            m0 = s & 0xff; m1 = (s >> 8) & 0xff;
        }
        pk0 = mi.x | (m0 ? (int)0x80000000 : 0);
        pk1 = mi.y | (m1 ? (int)0x80000000 : 0);
    }

    // ---- v = W_bil @ item_e  (v[d] = sum_e W[d][e] * ie[e]) ----
    float4 v = make_float4(0.f, 0.f, 0.f, 0.f);
#pragma unroll
    for (int e = 0; e < 32; e++) {
        float comp;
        switch (e & 3) {               // static after unroll
            case 0: comp = ie.x; break;
            case 1: comp = ie.y; break;
            case 2: comp = ie.z; break;
            default: comp = ie.w; break;
        }
        float iee = __shfl_sync(FULL, comp, sbase + (e >> 2));
        float4 wr = *reinterpret_cast<const float4*>(&Ws[e * 32 + sl * 4]);
        v.x = fmaf(wr.x, iee, v.x);
        v.y = fmaf(wr.y, iee, v.y);
        v.z = fmaf(wr.z, iee, v.z);
        v.w = fmaf(wr.w, iee, v.w);
    }

    // ---- member loop: score = u.v (width-8 butterfly), fu += mask*(score+b)*u ----
    float4 fu = make_float4(0.f, 0.f, 0.f, 0.f);
#pragma unroll
    for (int m = 0; m < 16; m++) {
        int pk = __shfl_sync(FULL, (m & 1) ? pk1 : pk0, sbase + (m >> 1));
        int uid = pk & 0x7fffffff;
        const float4 u = *reinterpret_cast<const float4*>(
            user_table + (size_t)uid * 32 + sl * 4);
        float p = u.x * v.x;
        p = fmaf(u.y, v.y, p);
        p = fmaf(u.z, v.z, p);
        p = fmaf(u.w, v.w, p);
        p += __shfl_xor_sync(FULL, p, 1);
        p += __shfl_xor_sync(FULL, p, 2);
        p += __shfl_xor_sync(FULL, p, 4);
        float w = (pk < 0) ? (p + bbil) : 0.0f;
        fu.x = fmaf(w, u.x, fu.x);
        fu.y = fmaf(w, u.y, fu.y);
        fu.z = fmaf(w, u.z, fu.z);
        fu.w = fmaf(w, u.w, fu.w);
    }

    // ---- MLP: x = [fu*ie | fu | ie] (96), h = relu(x W1^T + b1), y = sigmoid(h W2^T + b2)
    const float4 pr = make_float4(fu.x * ie.x, fu.y * ie.y, fu.z * ie.z, fu.w * ie.w);
    float h[8];
#pragma unroll
    for (int j = 0; j < 8; j++) {
        const float4 wA = *reinterpret_cast<const float4*>(&W1s[j * 96 + sl * 4]);
        const float4 wB = *reinterpret_cast<const float4*>(&W1s[j * 96 + 32 + sl * 4]);
        const float4 wC = *reinterpret_cast<const float4*>(&W1s[j * 96 + 64 + sl * 4]);
        float t = wA.x * pr.x;
        t = fmaf(wA.y, pr.y, t);
        t = fmaf(wA.z, pr.z, t);
        t = fmaf(wA.w, pr.w, t);
        t = fmaf(wB.x, fu.x, t);
        t = fmaf(wB.y, fu.y, t);
        t = fmaf(wB.z, fu.z, t);
        t = fmaf(wB.w, fu.w, t);
        t = fmaf(wC.x, ie.x, t);
        t = fmaf(wC.y, ie.y, t);
        t = fmaf(wC.z, ie.z, t);
        t = fmaf(wC.w, ie.w, t);
        h[j] = t;
    }
#pragma unroll
    for (int s = 1; s <= 4; s <<= 1) {
#pragma unroll
        for (int j = 0; j < 8; j++)
            h[j] += __shfl_xor_sync(FULL, h[j], s);
    }
    if (sl == 0 && b < B) {
        float acc = bb2;
#pragma unroll
        for (int j = 0; j < 8; j++)
            acc = fmaf(fmaxf(h[j] + b1s[j], 0.f), W2s[j], acc);
        out[b] = 1.0f / (1.0f + expf(-acc));
    }
}

extern "C" void kernel_launch(void* const* d_in, const int* in_sizes, int n_in,
                              void* d_out, int out_size) {
    // metadata order:
    // 0 item_inputs(i32) 1 member_ids(i32) 2 member_mask(bool) 3 user_table(f32)
    // 4 item_table(f32) 5 W_bil(f32) 6 b_bil(f32) 7 W1(f32) 8 b1(f32) 9 W2(f32) 10 b2(f32)
    const int*   item_inputs = (const int*)d_in[0];
    const int*   member_ids  = (const int*)d_in[1];
    const void*  member_mask = d_in[2];
    const float* user_table  = (const float*)d_in[3];
    const float* item_table  = (const float*)d_in[4];
    const float* W_bil       = (const float*)d_in[5];
    const float* b_bil       = (const float*)d_in[6];
    const float* W1          = (const float*)d_in[7];
    const float* b1          = (const float*)d_in[8];
    const float* W2          = (const float*)d_in[9];
    const float* b2          = (const float*)d_in[10];
    float* out = (float*)d_out;

    const int B = in_sizes[0];

    // Detect member_mask element width (numpy bool = 1 byte vs widened int32).
    int n_scan = in_sizes[2] / 4;          // ints readable under EITHER interpretation
    if (n_scan > 4096) n_scan = 4096;
    detect_mask_kernel<<<1, 256>>>((const int*)member_mask, n_scan);

    const int pairs_per_block = 32;        // 8 warps * 4 pairs
    const int grid = (B + pairs_per_block - 1) / pairs_per_block;
    bilinear_kernel<<<grid, 256>>>(item_inputs, member_ids, member_mask,
                                   user_table, item_table, W_bil, b_bil,
                                   b1, W1, W2, b2, out, B);
}